// round 9
// baseline (speedup 1.0000x reference)
#include <cuda_runtime.h>

// Hierarchical 2-additive Choquet integral, B=16, DEPTH=6.
// Big levels: 4 nodes per warp-group, grid-stride loop with register double-buffering
// (next group's 8 LDGs issued before current group's compute) to hide DRAM latency
// and keep the request stream dense. Pair LUT nibble-packed in smem.

#define NTH 136

__device__ float g_buf0[1 << 20];
__device__ float g_buf1[1 << 16];

__device__ __forceinline__ void fill_lut(unsigned int* s_lut4)
{
    const int t = threadIdx.x;
    if (t < NTH) {
        int i, j;
        if (t < 16) { i = t; j = t; }           // singleton -> min(x_k,x_k)=x_k
        else {
            int rem = t - 16; i = 0;
            #pragma unroll 1
            while (rem >= 15 - i) { rem -= 15 - i; ++i; }
            j = i + 1 + rem;                    // triu row-major == np.triu_indices
        }
        ((unsigned char*)s_lut4)[t] = (unsigned char)(i | (j << 4));
    }
}

__device__ __forceinline__ void accum4(float xv, float4 tv, unsigned int pk,
                                       float& num, float& den)
{
#pragma unroll
    for (int e = 0; e < 4; ++e) {
        const float tvk = (e == 0) ? tv.x : (e == 1) ? tv.y : (e == 2) ? tv.z : tv.w;
        const int b = (pk >> (8 * e)) & 0xff;
        const float a = __shfl_sync(0xffffffffu, xv, b & 15, 16);
        const float c = __shfl_sync(0xffffffffu, xv, b >> 4, 16);
        const float ex = __expf(tvk);
        den += ex;
        num = fmaf(ex, fminf(a, c), num);
    }
}

__device__ __forceinline__ void accum_tail(float xv, float sc, unsigned int lb,
                                           float& num, float& den)
{
    const float a = __shfl_sync(0xffffffffu, xv, lb & 15, 16);
    const float c = __shfl_sync(0xffffffffu, xv, lb >> 4, 16);
    const float ex = __expf(sc);            // sc = -1e30f on idle lanes -> ex = 0
    den += ex;
    num = fmaf(ex, fminf(a, c), num);
}

// One "group" = 4 nodes handled by one warp.
struct Grp {
    float  xv0, xv1;        // children: nodes (n0,n0+1) and (n0+2,n0+3)
    float4 t00, t01, t10, t11;
    float  s0, s1;          // scalar theta tail (lanes hl<8)
};

__device__ __forceinline__ Grp load_grp(const float* __restrict__ vals,
                                        const float* __restrict__ theta,
                                        int n0, int lane, int hl, int hi, bool act)
{
    Grp g;
    g.xv0 = __ldg(&vals[n0 * 16 + lane]);
    g.xv1 = __ldg(&vals[n0 * 16 + 32 + lane]);
    const float* rowA = theta + (size_t)(n0 + hi) * NTH;
    const float* rowB = theta + (size_t)(n0 + 2 + hi) * NTH;
    g.t00 = __ldg(&((const float4*)rowA)[hl]);
    g.t01 = __ldg(&((const float4*)rowA)[hl + 16]);
    g.t10 = __ldg(&((const float4*)rowB)[hl]);
    g.t11 = __ldg(&((const float4*)rowB)[hl + 16]);
    g.s0 = act ? __ldg(&rowA[128 + hl]) : -1e30f;
    g.s1 = act ? __ldg(&rowB[128 + hl]) : -1e30f;
    return g;
}

__device__ __forceinline__ void compute_grp(const Grp& g, float* __restrict__ out,
                                            int n0, int hl, int hi,
                                            unsigned int pkA, unsigned int pkB,
                                            unsigned int lbT)
{
    float num0 = 0.f, den0 = 0.f;
    accum4(g.xv0, g.t00, pkA, num0, den0);
    accum4(g.xv0, g.t01, pkB, num0, den0);
    accum_tail(g.xv0, g.s0, lbT, num0, den0);

    float num1 = 0.f, den1 = 0.f;
    accum4(g.xv1, g.t10, pkA, num1, den1);
    accum4(g.xv1, g.t11, pkB, num1, den1);
    accum_tail(g.xv1, g.s1, lbT, num1, den1);

#pragma unroll
    for (int o = 8; o > 0; o >>= 1) {
        num0 += __shfl_xor_sync(0xffffffffu, num0, o);
        den0 += __shfl_xor_sync(0xffffffffu, den0, o);
        num1 += __shfl_xor_sync(0xffffffffu, num1, o);
        den1 += __shfl_xor_sync(0xffffffffu, den1, o);
    }

    if (hl == 0) {
        out[n0 + hi]     = __fdividef(num0, den0);
        out[n0 + 2 + hi] = __fdividef(num1, den1);
    }
}

// ---------------------------------------------------------------------------
// Big-level kernel: grid-stride over 4-node groups, double-buffered prefetch.
// n_groups = n_nodes/4 (always a power of two here).
// ---------------------------------------------------------------------------
__global__ void __launch_bounds__(256)
choquet_pipe_kernel(const float* __restrict__ vals,
                    const float* __restrict__ theta,
                    float* __restrict__ out,
                    int n_groups)
{
    __shared__ unsigned int s_lut4[34];
    fill_lut(s_lut4);
    __syncthreads();

    const int lane = threadIdx.x & 31;
    const int hl   = lane & 15;
    const int hi   = lane >> 4;
    const bool act = hl < 8;

    const unsigned int pkA = s_lut4[hl];
    const unsigned int pkB = s_lut4[hl + 16];
    const unsigned int lbT = act ? ((const unsigned char*)s_lut4)[128 + hl] : 0u;

    const int W = (int)((gridDim.x * blockDim.x) >> 5);         // total warps
    int g = (int)((blockIdx.x * blockDim.x + threadIdx.x) >> 5);
    if (g >= n_groups) return;

    Grp bufA = load_grp(vals, theta, g * 4, lane, hl, hi, act);

    for (;;) {
        // prefetch next group, then compute current (ptxas front-batches the LDGs)
        int gn = g + W;
        if (gn < n_groups) {
            Grp bufB = load_grp(vals, theta, gn * 4, lane, hl, hi, act);
            compute_grp(bufA, out, g * 4, hl, hi, pkA, pkB, lbT);

            int gn2 = gn + W;
            if (gn2 < n_groups) {
                bufA = load_grp(vals, theta, gn2 * 4, lane, hl, hi, act);
                compute_grp(bufB, out, gn * 4, hl, hi, pkA, pkB, lbT);
                g = gn2;
            } else {
                compute_grp(bufB, out, gn * 4, hl, hi, pkA, pkB, lbT);
                return;
            }
        } else {
            compute_grp(bufA, out, g * 4, hl, hi, pkA, pkB, lbT);
            return;
        }
    }
}

// ---------------------------------------------------------------------------
// Levels 5 (16 nodes) + 6 (root): one small block.
// ---------------------------------------------------------------------------
__device__ __forceinline__ float choquet_half(float xv, const float* __restrict__ th,
                                              const unsigned int* s_lut4)
{
    const int hl = threadIdx.x & 15;
    float num = 0.f, den = 0.f;
    accum4(xv, __ldg(&((const float4*)th)[hl]),      s_lut4[hl],      num, den);
    accum4(xv, __ldg(&((const float4*)th)[hl + 16]), s_lut4[hl + 16], num, den);
    const bool act = hl < 8;
    accum_tail(xv, act ? __ldg(&th[128 + hl]) : -1e30f,
               act ? ((const unsigned char*)s_lut4)[128 + hl] : 0u, num, den);
#pragma unroll
    for (int o = 8; o > 0; o >>= 1) {
        num += __shfl_xor_sync(0xffffffffu, num, o);
        den += __shfl_xor_sync(0xffffffffu, den, o);
    }
    return __fdividef(num, den);
}

__global__ void __launch_bounds__(256)
choquet_l56_kernel(const float* __restrict__ v4,    // 256 level-4 outputs
                   const float* __restrict__ th5,   // 16 x 136
                   const float* __restrict__ th6,   // 1 x 136
                   float* __restrict__ out)
{
    __shared__ unsigned int s_lut4[34];
    __shared__ float s5[16];
    fill_lut(s_lut4);
    __syncthreads();

    const int warp = threadIdx.x >> 5;
    const int lane = threadIdx.x & 31;
    const int node = warp * 2 + (lane >> 4);

    const float xv = __ldg(&v4[warp * 32 + lane]);
    const float r  = choquet_half(xv, th5 + (size_t)node * NTH, s_lut4);
    if ((lane & 15) == 0) s5[node] = r;
    __syncthreads();

    if (warp == 0) {
        const float x2 = s5[lane & 15];              // both halves mirror the root
        const float root = choquet_half(x2, th6, s_lut4);
        if (lane == 0) out[0] = root;
    }
}

static inline void launch_level(const float* vals, const float* theta,
                                float* out, int n_nodes)
{
    const int n_groups = n_nodes / 4;
    int blocks = (n_groups + 7) / 8;     // 8 warps/block, 1 group/warp minimum
    if (blocks > 512) blocks = 512;      // grid-stride beyond this
    choquet_pipe_kernel<<<blocks, 256>>>(vals, theta, out, n_groups);
}

extern "C" void kernel_launch(void* const* d_in, const int* in_sizes, int n_in,
                              void* d_out, int out_size)
{
    (void)in_sizes; (void)n_in; (void)out_size;

    const float* x   = (const float*)d_in[0];
    const float* th1 = (const float*)d_in[1];
    const float* th2 = (const float*)d_in[2];
    const float* th3 = (const float*)d_in[3];
    const float* th4 = (const float*)d_in[4];
    const float* th5 = (const float*)d_in[5];
    const float* th6 = (const float*)d_in[6];
    float* out = (float*)d_out;

    float *b0, *b1;
    cudaGetSymbolAddress((void**)&b0, g_buf0);
    cudaGetSymbolAddress((void**)&b1, g_buf1);

    launch_level(x,  th1, b0, 1 << 20);   // level 1: 1,048,576 nodes
    launch_level(b0, th2, b1, 1 << 16);   // level 2: 65,536
    launch_level(b1, th3, b0, 1 << 12);   // level 3: 4,096
    launch_level(b0, th4, b1, 1 << 8);    // level 4: 256
    choquet_l56_kernel<<<1, 256>>>(b1, th5, th6, out);   // levels 5+6
}

// round 11
// speedup vs baseline: 1.3619x; 1.3619x over previous
#include <cuda_runtime.h>

// Hierarchical 2-additive Choquet integral, B=16, DEPTH=6.
// Big levels: 4 nodes per warp (two 16-lane halves x two node-pairs), all 8 global
// loads front-batched, regs ~32, occupancy-driven latency hiding (R6 structure).
// New vs R6: closed-form LUT fill (no serial loop) + merged num/den butterfly.

#define NTH 136

__device__ float g_buf0[1 << 20];
__device__ float g_buf1[1 << 16];

// Closed-form triu-index inversion: for rem in [0,120), find row i such that
// S(i) = 15i - i(i-1)/2 <= rem < S(i+1); j = i + 1 + (rem - S(i)).
__device__ __forceinline__ void fill_lut(unsigned int* s_lut4)
{
    const int t = threadIdx.x;
    if (t < NTH) {
        int i, j;
        if (t < 16) { i = t; j = t; }           // singleton -> min(x_k,x_k)=x_k
        else {
            const int rem = t - 16;
            int ii = (int)((31.0f - sqrtf(961.0f - 8.0f * (float)rem)) * 0.5f);
            int S = 15 * ii - (ii * (ii - 1)) / 2;
            if (rem < S) { --ii; S = 15 * ii - (ii * (ii - 1)) / 2; }
            else { const int S2 = S + (15 - ii); if (rem >= S2) { ++ii; S = S2; } }
            i = ii; j = ii + 1 + (rem - S);     // matches np.triu_indices order
        }
        ((unsigned char*)s_lut4)[t] = (unsigned char)(i | (j << 4));
    }
}

__device__ __forceinline__ void accum4(float xv, float4 tv, unsigned int pk,
                                       float& num, float& den)
{
#pragma unroll
    for (int e = 0; e < 4; ++e) {
        const float tvk = (e == 0) ? tv.x : (e == 1) ? tv.y : (e == 2) ? tv.z : tv.w;
        const int b = (pk >> (8 * e)) & 0xff;
        const float a = __shfl_sync(0xffffffffu, xv, b & 15, 16);
        const float c = __shfl_sync(0xffffffffu, xv, b >> 4, 16);
        const float ex = __expf(tvk);
        den += ex;
        num = fmaf(ex, fminf(a, c), num);
    }
}

__device__ __forceinline__ void accum_tail(float xv, float sc, unsigned int lb,
                                           float& num, float& den)
{
    const float a = __shfl_sync(0xffffffffu, xv, lb & 15, 16);
    const float c = __shfl_sync(0xffffffffu, xv, lb >> 4, 16);
    const float ex = __expf(sc);            // sc = -1e30f on idle lanes -> ex = 0
    den += ex;
    num = fmaf(ex, fminf(a, c), num);
}

// Merged butterfly: reduce num over each 16-half and den over each 16-half using
// 6 shfl instead of 8. On return, lanes hl<8 hold (v=num_total, w=den_total).
__device__ __forceinline__ void reduce_merged(float num, float den, int hl,
                                              float& v, float& w)
{
    num += __shfl_xor_sync(0xffffffffu, num, 8);
    den += __shfl_xor_sync(0xffffffffu, den, 8);
    v = (hl < 8) ? num : den;               // low 8: num partial, high 8: den partial
    v += __shfl_xor_sync(0xffffffffu, v, 4);
    v += __shfl_xor_sync(0xffffffffu, v, 2);
    v += __shfl_xor_sync(0xffffffffu, v, 1);
    w = __shfl_xor_sync(0xffffffffu, v, 8); // fetch opposite subgroup's total
}

// ---------------------------------------------------------------------------
// Big-level kernel: 4 nodes per warp, all global loads issued up front.
// Requires n_nodes % 4 == 0.
// ---------------------------------------------------------------------------
__global__ void __launch_bounds__(256)
choquet4_kernel(const float* __restrict__ vals,
                const float* __restrict__ theta,
                float* __restrict__ out,
                int n_nodes)
{
    __shared__ unsigned int s_lut4[34];
    fill_lut(s_lut4);
    __syncthreads();

    const int gw   = (int)((blockIdx.x * blockDim.x + threadIdx.x) >> 5);
    const int n0   = gw * 4;
    if (n0 >= n_nodes) return;
    const int lane = threadIdx.x & 31;
    const int hl   = lane & 15;
    const int hi   = lane >> 4;
    const bool act = hl < 8;

    // ---- front-batched loads (8 independent LDGs) ----
    const float xv0 = __ldg(&vals[n0 * 16 + lane]);        // children of nodes n0, n0+1
    const float xv1 = __ldg(&vals[n0 * 16 + 32 + lane]);   // children of nodes n0+2, n0+3

    const float* rowA = theta + (size_t)(n0 + hi) * NTH;
    const float* rowB = theta + (size_t)(n0 + 2 + hi) * NTH;
    const float4 t00 = __ldg(&((const float4*)rowA)[hl]);
    const float4 t01 = __ldg(&((const float4*)rowA)[hl + 16]);
    const float4 t10 = __ldg(&((const float4*)rowB)[hl]);
    const float4 t11 = __ldg(&((const float4*)rowB)[hl + 16]);
    const float s0 = act ? __ldg(&rowA[128 + hl]) : -1e30f;
    const float s1 = act ? __ldg(&rowB[128 + hl]) : -1e30f;

    // ---- LUT words ----
    const unsigned int pkA = s_lut4[hl];
    const unsigned int pkB = s_lut4[hl + 16];
    const unsigned int lbT = act ? ((const unsigned char*)s_lut4)[128 + hl] : 0u;

    // ---- pair 0 (nodes n0, n0+1) ----
    float num0 = 0.f, den0 = 0.f;
    accum4(xv0, t00, pkA, num0, den0);
    accum4(xv0, t01, pkB, num0, den0);
    accum_tail(xv0, s0, lbT, num0, den0);

    // ---- pair 1 (nodes n0+2, n0+3) ----
    float num1 = 0.f, den1 = 0.f;
    accum4(xv1, t10, pkA, num1, den1);
    accum4(xv1, t11, pkB, num1, den1);
    accum_tail(xv1, s1, lbT, num1, den1);

    // ---- merged reductions ----
    float v0, w0, v1, w1;
    reduce_merged(num0, den0, hl, v0, w0);
    reduce_merged(num1, den1, hl, v1, w1);

    if (hl == 0) {
        out[n0 + hi]     = __fdividef(v0, w0);
        out[n0 + 2 + hi] = __fdividef(v1, w1);
    }
}

// ---------------------------------------------------------------------------
// Fused tail: levels 4 (256), 5 (16), 6 (1) in one 1024-thread block.
// ---------------------------------------------------------------------------
__device__ __forceinline__ float choquet_warp2(float xv, const float* __restrict__ th,
                                               const unsigned int* s_lut4)
{
    const int hl = threadIdx.x & 15;
    float num = 0.f, den = 0.f;
    accum4(xv, __ldg(&((const float4*)th)[hl]),      s_lut4[hl],      num, den);
    accum4(xv, __ldg(&((const float4*)th)[hl + 16]), s_lut4[hl + 16], num, den);
    const bool act = hl < 8;
    accum_tail(xv, act ? __ldg(&th[128 + hl]) : -1e30f,
               act ? ((const unsigned char*)s_lut4)[128 + hl] : 0u, num, den);
    float v, w;
    reduce_merged(num, den, hl, v, w);
    return __fdividef(v, w);               // valid on lanes hl<8 (used at hl==0)
}

__global__ void __launch_bounds__(1024)
choquet_tail_kernel(const float* __restrict__ v3,    // 4096 level-3 outputs
                    const float* __restrict__ th4,   // 256 x 136
                    const float* __restrict__ th5,   // 16 x 136
                    const float* __restrict__ th6,   // 1 x 136
                    float* __restrict__ out)
{
    __shared__ unsigned int s_lut4[34];
    __shared__ float s4[256];
    __shared__ float s5[16];
    fill_lut(s_lut4);
    __syncthreads();

    const int warp = threadIdx.x >> 5;   // 0..31
    const int lane = threadIdx.x & 31;
    const int hi   = lane >> 4;

    // level 4: 256 nodes, 64 per pass (32 warps x 2 nodes), 4 passes
#pragma unroll
    for (int it = 0; it < 4; ++it) {
        const int node = it * 64 + warp * 2 + hi;
        const float xv = __ldg(&v3[it * 1024 + warp * 32 + lane]);
        const float r  = choquet_warp2(xv, th4 + (size_t)node * NTH, s_lut4);
        if ((lane & 15) == 0) s4[node] = r;
    }
    __syncthreads();

    // level 5: 16 nodes on warps 0..7
    if (warp < 8) {
        const int node = warp * 2 + hi;
        const float xv = s4[warp * 32 + lane];
        const float r  = choquet_warp2(xv, th5 + (size_t)node * NTH, s_lut4);
        if ((lane & 15) == 0) s5[node] = r;
    }
    __syncthreads();

    // level 6: root on warp 0 (both halves mirror it)
    if (warp == 0) {
        const float xv = s5[lane & 15];
        const float root = choquet_warp2(xv, th6, s_lut4);
        if (lane == 0) out[0] = root;
    }
}

static inline void launch_level(const float* vals, const float* theta,
                                float* out, int n_nodes)
{
    const int warps = n_nodes / 4;                 // 4 nodes per warp
    const int blocks = (warps + 7) / 8;            // 8 warps per block
    choquet4_kernel<<<blocks, 256>>>(vals, theta, out, n_nodes);
}

extern "C" void kernel_launch(void* const* d_in, const int* in_sizes, int n_in,
                              void* d_out, int out_size)
{
    (void)in_sizes; (void)n_in; (void)out_size;

    const float* x   = (const float*)d_in[0];
    const float* th1 = (const float*)d_in[1];
    const float* th2 = (const float*)d_in[2];
    const float* th3 = (const float*)d_in[3];
    const float* th4 = (const float*)d_in[4];
    const float* th5 = (const float*)d_in[5];
    const float* th6 = (const float*)d_in[6];
    float* out = (float*)d_out;

    float *b0, *b1;
    cudaGetSymbolAddress((void**)&b0, g_buf0);
    cudaGetSymbolAddress((void**)&b1, g_buf1);

    launch_level(x,  th1, b0, 1 << 20);   // level 1: 1,048,576 nodes
    launch_level(b0, th2, b1, 1 << 16);   // level 2: 65,536
    launch_level(b1, th3, b0, 1 << 12);   // level 3: 4,096
    choquet_tail_kernel<<<1, 1024>>>(b0, th4, th5, th6, out);   // levels 4-6
}

// round 12
// speedup vs baseline: 1.3774x; 1.0114x over previous
#include <cuda_runtime.h>

// Hierarchical 2-additive Choquet integral, B=16, DEPTH=6.
// Levels 1-4: choquet4_kernel — 4 nodes/warp, front-batched loads, regs ~32.
// Levels 5-6: one small block (two serial node evals).

#define NTH 136

__device__ float g_buf0[1 << 20];
__device__ float g_buf1[1 << 16];

// Closed-form triu-index inversion: for rem in [0,120), find row i such that
// S(i) = 15i - i(i-1)/2 <= rem < S(i+1); j = i + 1 + (rem - S(i)).
__device__ __forceinline__ void fill_lut(unsigned int* s_lut4)
{
    const int t = threadIdx.x;
    if (t < NTH) {
        int i, j;
        if (t < 16) { i = t; j = t; }           // singleton -> min(x_k,x_k)=x_k
        else {
            const int rem = t - 16;
            int ii = (int)((31.0f - sqrtf(961.0f - 8.0f * (float)rem)) * 0.5f);
            int S = 15 * ii - (ii * (ii - 1)) / 2;
            if (rem < S) { --ii; S = 15 * ii - (ii * (ii - 1)) / 2; }
            else { const int S2 = S + (15 - ii); if (rem >= S2) { ++ii; S = S2; } }
            i = ii; j = ii + 1 + (rem - S);     // matches np.triu_indices order
        }
        ((unsigned char*)s_lut4)[t] = (unsigned char)(i | (j << 4));
    }
}

__device__ __forceinline__ void accum4(float xv, float4 tv, unsigned int pk,
                                       float& num, float& den)
{
#pragma unroll
    for (int e = 0; e < 4; ++e) {
        const float tvk = (e == 0) ? tv.x : (e == 1) ? tv.y : (e == 2) ? tv.z : tv.w;
        const int b = (pk >> (8 * e)) & 0xff;
        const float a = __shfl_sync(0xffffffffu, xv, b & 15, 16);
        const float c = __shfl_sync(0xffffffffu, xv, b >> 4, 16);
        const float ex = __expf(tvk);
        den += ex;
        num = fmaf(ex, fminf(a, c), num);
    }
}

__device__ __forceinline__ void accum_tail(float xv, float sc, unsigned int lb,
                                           float& num, float& den)
{
    const float a = __shfl_sync(0xffffffffu, xv, lb & 15, 16);
    const float c = __shfl_sync(0xffffffffu, xv, lb >> 4, 16);
    const float ex = __expf(sc);            // sc = -1e30f on idle lanes -> ex = 0
    den += ex;
    num = fmaf(ex, fminf(a, c), num);
}

// Merged butterfly: 6 shfl instead of 8. On return lanes hl<8 hold
// (v = num_total, w = den_total) of their 16-lane half.
__device__ __forceinline__ void reduce_merged(float num, float den, int hl,
                                              float& v, float& w)
{
    num += __shfl_xor_sync(0xffffffffu, num, 8);
    den += __shfl_xor_sync(0xffffffffu, den, 8);
    v = (hl < 8) ? num : den;
    v += __shfl_xor_sync(0xffffffffu, v, 4);
    v += __shfl_xor_sync(0xffffffffu, v, 2);
    v += __shfl_xor_sync(0xffffffffu, v, 1);
    w = __shfl_xor_sync(0xffffffffu, v, 8);
}

// ---------------------------------------------------------------------------
// Big-level kernel: 4 nodes per warp, all global loads issued up front.
// Requires n_nodes % 4 == 0.
// ---------------------------------------------------------------------------
__global__ void __launch_bounds__(256)
choquet4_kernel(const float* __restrict__ vals,
                const float* __restrict__ theta,
                float* __restrict__ out,
                int n_nodes)
{
    __shared__ unsigned int s_lut4[34];
    fill_lut(s_lut4);
    __syncthreads();

    const int gw   = (int)((blockIdx.x * blockDim.x + threadIdx.x) >> 5);
    const int n0   = gw * 4;
    if (n0 >= n_nodes) return;
    const int lane = threadIdx.x & 31;
    const int hl   = lane & 15;
    const int hi   = lane >> 4;
    const bool act = hl < 8;

    // ---- front-batched loads (10 independent LDGs) ----
    const float xv0 = __ldg(&vals[n0 * 16 + lane]);        // children of nodes n0, n0+1
    const float xv1 = __ldg(&vals[n0 * 16 + 32 + lane]);   // children of nodes n0+2, n0+3

    const float* rowA = theta + (size_t)(n0 + hi) * NTH;
    const float* rowB = theta + (size_t)(n0 + 2 + hi) * NTH;
    const float4 t00 = __ldg(&((const float4*)rowA)[hl]);
    const float4 t01 = __ldg(&((const float4*)rowA)[hl + 16]);
    const float4 t10 = __ldg(&((const float4*)rowB)[hl]);
    const float4 t11 = __ldg(&((const float4*)rowB)[hl + 16]);
    const float s0 = act ? __ldg(&rowA[128 + hl]) : -1e30f;
    const float s1 = act ? __ldg(&rowB[128 + hl]) : -1e30f;

    // ---- LUT words ----
    const unsigned int pkA = s_lut4[hl];
    const unsigned int pkB = s_lut4[hl + 16];
    const unsigned int lbT = act ? ((const unsigned char*)s_lut4)[128 + hl] : 0u;

    // ---- pair 0 (nodes n0, n0+1) ----
    float num0 = 0.f, den0 = 0.f;
    accum4(xv0, t00, pkA, num0, den0);
    accum4(xv0, t01, pkB, num0, den0);
    accum_tail(xv0, s0, lbT, num0, den0);

    // ---- pair 1 (nodes n0+2, n0+3) ----
    float num1 = 0.f, den1 = 0.f;
    accum4(xv1, t10, pkA, num1, den1);
    accum4(xv1, t11, pkB, num1, den1);
    accum_tail(xv1, s1, lbT, num1, den1);

    // ---- merged reductions ----
    float v0, w0, v1, w1;
    reduce_merged(num0, den0, hl, v0, w0);
    reduce_merged(num1, den1, hl, v1, w1);

    if (hl == 0) {
        out[n0 + hi]     = __fdividef(v0, w0);
        out[n0 + 2 + hi] = __fdividef(v1, w1);
    }
}

// ---------------------------------------------------------------------------
// Levels 5 (16 nodes) + 6 (root): one small block, two short serial stages.
// ---------------------------------------------------------------------------
__device__ __forceinline__ float choquet_half(float xv, const float* __restrict__ th,
                                              const unsigned int* s_lut4)
{
    const int hl = threadIdx.x & 15;
    float num = 0.f, den = 0.f;
    accum4(xv, __ldg(&((const float4*)th)[hl]),      s_lut4[hl],      num, den);
    accum4(xv, __ldg(&((const float4*)th)[hl + 16]), s_lut4[hl + 16], num, den);
    const bool act = hl < 8;
    accum_tail(xv, act ? __ldg(&th[128 + hl]) : -1e30f,
               act ? ((const unsigned char*)s_lut4)[128 + hl] : 0u, num, den);
    float v, w;
    reduce_merged(num, den, hl, v, w);
    return __fdividef(v, w);               // valid on lanes hl<8 (used at hl==0)
}

__global__ void __launch_bounds__(256)
choquet_l56_kernel(const float* __restrict__ v4,    // 256 level-4 outputs
                   const float* __restrict__ th5,   // 16 x 136
                   const float* __restrict__ th6,   // 1 x 136
                   float* __restrict__ out)
{
    __shared__ unsigned int s_lut4[34];
    __shared__ float s5[16];
    fill_lut(s_lut4);
    __syncthreads();

    const int warp = threadIdx.x >> 5;   // 0..7
    const int lane = threadIdx.x & 31;
    const int node = warp * 2 + (lane >> 4);

    // level 5: 16 nodes across 8 warps (2 per warp)
    const float xv = __ldg(&v4[warp * 32 + lane]);
    const float r  = choquet_half(xv, th5 + (size_t)node * NTH, s_lut4);
    if ((lane & 15) == 0) s5[node] = r;
    __syncthreads();

    // level 6: root on warp 0 (both halves mirror it)
    if (warp == 0) {
        const float x2 = s5[lane & 15];
        const float root = choquet_half(x2, th6, s_lut4);
        if (lane == 0) out[0] = root;
    }
}

static inline void launch_level(const float* vals, const float* theta,
                                float* out, int n_nodes)
{
    const int warps = n_nodes / 4;                 // 4 nodes per warp
    const int blocks = (warps + 7) / 8;            // 8 warps per block
    choquet4_kernel<<<blocks, 256>>>(vals, theta, out, n_nodes);
}

extern "C" void kernel_launch(void* const* d_in, const int* in_sizes, int n_in,
                              void* d_out, int out_size)
{
    (void)in_sizes; (void)n_in; (void)out_size;

    const float* x   = (const float*)d_in[0];
    const float* th1 = (const float*)d_in[1];
    const float* th2 = (const float*)d_in[2];
    const float* th3 = (const float*)d_in[3];
    const float* th4 = (const float*)d_in[4];
    const float* th5 = (const float*)d_in[5];
    const float* th6 = (const float*)d_in[6];
    float* out = (float*)d_out;

    float *b0, *b1;
    cudaGetSymbolAddress((void**)&b0, g_buf0);
    cudaGetSymbolAddress((void**)&b1, g_buf1);

    launch_level(x,  th1, b0, 1 << 20);   // level 1: 1,048,576 nodes
    launch_level(b0, th2, b1, 1 << 16);   // level 2: 65,536
    launch_level(b1, th3, b0, 1 << 12);   // level 3: 4,096
    launch_level(b0, th4, b1, 1 << 8);    // level 4: 256  (8 blocks, parallel)
    choquet_l56_kernel<<<1, 256>>>(b1, th5, th6, out);      // levels 5+6
}

// round 13
// speedup vs baseline: 1.4407x; 1.0460x over previous
#include <cuda_runtime.h>

// Hierarchical 2-additive Choquet integral, B=16, DEPTH=6.
// Fused pairs of levels: one block = 32 level-l nodes (8 warps x 4 nodes, smem)
// -> 2 level-(l+1) nodes (warp 0 epilogue). 3 launches total:
//   fused(x, th1, th2)  -> b1 (65536 level-2 outputs)
//   fused(b1, th3, th4) -> b0 (256 level-4 outputs)
//   l56(b0, th5, th6)   -> out (root)

#define NTH 136

__device__ float g_buf0[1 << 20];
__device__ float g_buf1[1 << 16];

// Closed-form triu-index inversion (matches np.triu_indices(16, k=1) order).
__device__ __forceinline__ void fill_lut(unsigned int* s_lut4)
{
    const int t = threadIdx.x;
    if (t < NTH) {
        int i, j;
        if (t < 16) { i = t; j = t; }           // singleton -> min(x_k,x_k)=x_k
        else {
            const int rem = t - 16;
            int ii = (int)((31.0f - sqrtf(961.0f - 8.0f * (float)rem)) * 0.5f);
            int S = 15 * ii - (ii * (ii - 1)) / 2;
            if (rem < S) { --ii; S = 15 * ii - (ii * (ii - 1)) / 2; }
            else { const int S2 = S + (15 - ii); if (rem >= S2) { ++ii; S = S2; } }
            i = ii; j = ii + 1 + (rem - S);
        }
        ((unsigned char*)s_lut4)[t] = (unsigned char)(i | (j << 4));
    }
}

__device__ __forceinline__ void accum4(float xv, float4 tv, unsigned int pk,
                                       float& num, float& den)
{
#pragma unroll
    for (int e = 0; e < 4; ++e) {
        const float tvk = (e == 0) ? tv.x : (e == 1) ? tv.y : (e == 2) ? tv.z : tv.w;
        const int b = (pk >> (8 * e)) & 0xff;
        const float a = __shfl_sync(0xffffffffu, xv, b & 15, 16);
        const float c = __shfl_sync(0xffffffffu, xv, b >> 4, 16);
        const float ex = __expf(tvk);
        den += ex;
        num = fmaf(ex, fminf(a, c), num);
    }
}

__device__ __forceinline__ void accum_tail(float xv, float sc, unsigned int lb,
                                           float& num, float& den)
{
    const float a = __shfl_sync(0xffffffffu, xv, lb & 15, 16);
    const float c = __shfl_sync(0xffffffffu, xv, lb >> 4, 16);
    const float ex = __expf(sc);            // sc = -1e30f on idle lanes -> ex = 0
    den += ex;
    num = fmaf(ex, fminf(a, c), num);
}

// Merged butterfly: on return lanes hl<8 hold (v=num_total, w=den_total).
__device__ __forceinline__ void reduce_merged(float num, float den, int hl,
                                              float& v, float& w)
{
    num += __shfl_xor_sync(0xffffffffu, num, 8);
    den += __shfl_xor_sync(0xffffffffu, den, 8);
    v = (hl < 8) ? num : den;
    v += __shfl_xor_sync(0xffffffffu, v, 4);
    v += __shfl_xor_sync(0xffffffffu, v, 2);
    v += __shfl_xor_sync(0xffffffffu, v, 1);
    w = __shfl_xor_sync(0xffffffffu, v, 8);
}

// One node per 16-lane half: xv = this lane's child, th = theta row (16B aligned).
// Returns num/den on lanes hl<8.
__device__ __forceinline__ float choquet_half(float xv, const float* __restrict__ th,
                                              const unsigned int* s_lut4)
{
    const int hl = threadIdx.x & 15;
    float num = 0.f, den = 0.f;
    accum4(xv, __ldg(&((const float4*)th)[hl]),      s_lut4[hl],      num, den);
    accum4(xv, __ldg(&((const float4*)th)[hl + 16]), s_lut4[hl + 16], num, den);
    const bool act = hl < 8;
    accum_tail(xv, act ? __ldg(&th[128 + hl]) : -1e30f,
               act ? ((const unsigned char*)s_lut4)[128 + hl] : 0u, num, den);
    float v, w;
    reduce_merged(num, den, hl, v, w);
    return __fdividef(v, w);
}

// ---------------------------------------------------------------------------
// Fused two-level kernel. Block = 2 upper nodes = 32 lower nodes.
// grid.x = n_upper_nodes / 2.  vals: children of the lower level.
// ---------------------------------------------------------------------------
__global__ void __launch_bounds__(256)
choquet_fused2_kernel(const float* __restrict__ vals,
                      const float* __restrict__ thL,   // lower-level thetas
                      const float* __restrict__ thU,   // upper-level thetas
                      float* __restrict__ out)
{
    __shared__ unsigned int s_lut4[34];
    __shared__ float s1[32];                 // lower-level outputs (block-local)
    fill_lut(s_lut4);
    __syncthreads();

    const int lane = threadIdx.x & 31;
    const int warp = threadIdx.x >> 5;       // 0..7
    const int hl   = lane & 15;
    const int hi   = lane >> 4;
    const bool act = hl < 8;

    // ---- lower level: 4 nodes per warp (identical hot loop to choquet4) ----
    const int n0   = blockIdx.x * 32 + warp * 4;   // global lower-node base
    const int nl   = warp * 4;                     // block-local base

    const float xv0 = __ldg(&vals[n0 * 16 + lane]);
    const float xv1 = __ldg(&vals[n0 * 16 + 32 + lane]);

    const float* rowA = thL + (size_t)(n0 + hi) * NTH;
    const float* rowB = thL + (size_t)(n0 + 2 + hi) * NTH;
    const float4 t00 = __ldg(&((const float4*)rowA)[hl]);
    const float4 t01 = __ldg(&((const float4*)rowA)[hl + 16]);
    const float4 t10 = __ldg(&((const float4*)rowB)[hl]);
    const float4 t11 = __ldg(&((const float4*)rowB)[hl + 16]);
    const float s0 = act ? __ldg(&rowA[128 + hl]) : -1e30f;
    const float s1v = act ? __ldg(&rowB[128 + hl]) : -1e30f;

    const unsigned int pkA = s_lut4[hl];
    const unsigned int pkB = s_lut4[hl + 16];
    const unsigned int lbT = act ? ((const unsigned char*)s_lut4)[128 + hl] : 0u;

    float num0 = 0.f, den0 = 0.f;
    accum4(xv0, t00, pkA, num0, den0);
    accum4(xv0, t01, pkB, num0, den0);
    accum_tail(xv0, s0, lbT, num0, den0);

    float num1 = 0.f, den1 = 0.f;
    accum4(xv1, t10, pkA, num1, den1);
    accum4(xv1, t11, pkB, num1, den1);
    accum_tail(xv1, s1v, lbT, num1, den1);

    float v0, w0, v1, w1;
    reduce_merged(num0, den0, hl, v0, w0);
    reduce_merged(num1, den1, hl, v1, w1);

    if (hl == 0) {
        s1[nl + hi]     = __fdividef(v0, w0);
        s1[nl + 2 + hi] = __fdividef(v1, w1);
    }
    __syncthreads();

    // ---- upper level: warp 0 computes the block's 2 upper nodes ----
    if (warp == 0) {
        const int nodeU = blockIdx.x * 2 + hi;
        const float xv = s1[hi * 16 + hl];
        const float r  = choquet_half(xv, thU + (size_t)nodeU * NTH, s_lut4);
        if (hl == 0) out[nodeU] = r;
    }
}

// ---------------------------------------------------------------------------
// Levels 5 (16 nodes) + 6 (root): one small block.
// ---------------------------------------------------------------------------
__global__ void __launch_bounds__(256)
choquet_l56_kernel(const float* __restrict__ v4,    // 256 level-4 outputs
                   const float* __restrict__ th5,   // 16 x 136
                   const float* __restrict__ th6,   // 1 x 136
                   float* __restrict__ out)
{
    __shared__ unsigned int s_lut4[34];
    __shared__ float s5[16];
    fill_lut(s_lut4);
    __syncthreads();

    const int warp = threadIdx.x >> 5;   // 0..7
    const int lane = threadIdx.x & 31;
    const int node = warp * 2 + (lane >> 4);

    const float xv = __ldg(&v4[warp * 32 + lane]);
    const float r  = choquet_half(xv, th5 + (size_t)node * NTH, s_lut4);
    if ((lane & 15) == 0) s5[node] = r;
    __syncthreads();

    if (warp == 0) {
        const float x2 = s5[lane & 15];
        const float root = choquet_half(x2, th6, s_lut4);
        if (lane == 0) out[0] = root;
    }
}

extern "C" void kernel_launch(void* const* d_in, const int* in_sizes, int n_in,
                              void* d_out, int out_size)
{
    (void)in_sizes; (void)n_in; (void)out_size;

    const float* x   = (const float*)d_in[0];
    const float* th1 = (const float*)d_in[1];
    const float* th2 = (const float*)d_in[2];
    const float* th3 = (const float*)d_in[3];
    const float* th4 = (const float*)d_in[4];
    const float* th5 = (const float*)d_in[5];
    const float* th6 = (const float*)d_in[6];
    float* out = (float*)d_out;

    float *b0, *b1;
    cudaGetSymbolAddress((void**)&b0, g_buf0);
    cudaGetSymbolAddress((void**)&b1, g_buf1);

    // levels 1+2: 1,048,576 -> 65,536 (32768 blocks)
    choquet_fused2_kernel<<<32768, 256>>>(x, th1, th2, b1);
    // levels 3+4: 65,536/16=4096 lower nodes -> 256 upper (128 blocks)
    choquet_fused2_kernel<<<128, 256>>>(b1, th3, th4, b0);
    // levels 5+6
    choquet_l56_kernel<<<1, 256>>>(b0, th5, th6, out);
}